// round 1
// baseline (speedup 1.0000x reference)
#include <cuda_runtime.h>
#include <math.h>

#define BB 2
#define LL 4096
#define CC 1024
#define NHH 16
#define DHH 64
#define MM 1638
#define C3 3072
#define LSPLIT 16

// ---------------- scratch (device globals; no allocations allowed) ----------
__device__ double g_part[LSPLIT * BB * CC];
__device__ float  g_mean[BB * CC];
__device__ float  g_mse[BB * LL];
__device__ int    g_idx[BB * MM];
__device__ float  g_bias3[C3];
__device__ float  g_scl[NHH];
__device__ float  g_qkv[(size_t)BB * MM * C3];
__device__ float  g_q[(size_t)BB * NHH * MM * DHH];
__device__ float  g_k[(size_t)BB * NHH * MM * DHH];
__device__ float  g_v[(size_t)BB * NHH * MM * DHH];
__device__ float  g_ao[(size_t)BB * MM * CC];
__device__ float  g_po[(size_t)BB * MM * CC];

// ---------------- mean over L (split-L partials, deterministic) -------------
__global__ void k_mean_part(const float* __restrict__ x) {
    int b = blockIdx.y;
    int z = blockIdx.z;
    int c = blockIdx.x * 256 + threadIdx.x;
    const float* xb = x + (size_t)b * LL * CC + (size_t)z * (LL / LSPLIT) * CC + c;
    double acc = 0.0;
#pragma unroll 8
    for (int l = 0; l < LL / LSPLIT; l++) acc += (double)xb[(size_t)l * CC];
    g_part[((size_t)z * BB + b) * CC + c] = acc;
}

__global__ void k_mean_final() {
    int i = blockIdx.x * 256 + threadIdx.x;   // over BB*CC
    int b = i / CC, c = i % CC;
    double acc = 0.0;
#pragma unroll
    for (int z = 0; z < LSPLIT; z++) acc += g_part[((size_t)z * BB + b) * CC + c];
    g_mean[i] = (float)(acc / (double)LL);
}

// ---------------- mse per token ---------------------------------------------
__global__ void k_mse(const float* __restrict__ x) {
    int l = blockIdx.x, b = blockIdx.y, t = threadIdx.x;
    const float* row = x + ((size_t)b * LL + l) * CC;
    const float* mb  = g_mean + b * CC;
    double acc = 0.0;
    for (int c = t; c < CC; c += 256) {
        float d = row[c] - mb[c];
        acc += (double)d * (double)d;
    }
    __shared__ double s[256];
    s[t] = acc;
    __syncthreads();
    for (int o = 128; o > 0; o >>= 1) {
        if (t < o) s[t] += s[t + o];
        __syncthreads();
    }
    if (t == 0) g_mse[b * LL + l] = (float)s[0];
}

// ---------------- top-1638 via bitonic sort (desc value, asc index ties) ----
__global__ void k_topk() {
    __shared__ float sv[LL];
    __shared__ int   si[LL];
    int b = blockIdx.x;
    for (int i = threadIdx.x; i < LL; i += blockDim.x) {
        sv[i] = g_mse[b * LL + i];
        si[i] = i;
    }
    __syncthreads();
    for (int k = 2; k <= LL; k <<= 1) {
        for (int j = k >> 1; j > 0; j >>= 1) {
            for (int i = threadIdx.x; i < LL; i += blockDim.x) {
                int ixj = i ^ j;
                if (ixj > i) {
                    float va = sv[i], vb = sv[ixj];
                    int   ia = si[i], ib = si[ixj];
                    // desired order: larger value first; tie -> smaller index first
                    bool a_before_b = (va > vb) || (va == vb && ia < ib);
                    bool up = ((i & k) == 0);
                    bool doswap = up ? (!a_before_b) : a_before_b;
                    if (doswap) {
                        sv[i] = vb; sv[ixj] = va;
                        si[i] = ib; si[ixj] = ia;
                    }
                }
            }
            __syncthreads();
        }
    }
    for (int i = threadIdx.x; i < MM; i += blockDim.x) g_idx[b * MM + i] = si[i];
}

// ---------------- bias concat + per-head scale -------------------------------
__global__ void k_bias3(const float* __restrict__ qb, const float* __restrict__ vb,
                        const float* __restrict__ sml) {
    int n = blockIdx.x * 256 + threadIdx.x;
    if (n < C3) {
        float v = 0.f;
        if (n < CC) v = qb[n];
        else if (n >= 2 * CC) v = vb[n - 2 * CC];
        g_bias3[n] = v;
    }
    if (n < NHH) g_scl[n] = expf(fminf(sml[n], 4.6051702f));   // exp(min(., ln 100))
}

// ---------------- tiled fp32 GEMM: C = gather(A) @ W^T + bias ----------------
// mode 0: qkv  (A = x rows gathered by g_idx, N = 3072, out g_qkv, bias g_bias3)
// mode 1: proj (A = g_ao, N = 1024, out g_po, bias = biasin)
__global__ void k_gemm(int mode, const float* __restrict__ xin,
                       const float* __restrict__ W, const float* __restrict__ biasin) {
    const float* A; const int* gather; const float* bias; float* Cout;
    int N; long aStr, cStr;
    if (mode == 0) {
        A = xin; gather = g_idx; bias = g_bias3; Cout = g_qkv;
        N = C3; aStr = (long)LL * CC; cStr = (long)MM * C3;
    } else {
        A = g_ao; gather = 0; bias = biasin; Cout = g_po;
        N = CC; aStr = (long)MM * CC; cStr = (long)MM * CC;
    }
    const int K = CC;
    int b = blockIdx.z;
    const float* Ab = A + (long)b * aStr;
    float*       Cb = Cout + (long)b * cStr;
    const int*   gb = gather ? gather + b * MM : 0;

    int m0 = blockIdx.y * 64, n0 = blockIdx.x * 64;
    __shared__ float As[16][64];
    __shared__ float Bs[16][64];
    int tid = threadIdx.x;
    int tx = tid & 15, ty = tid >> 4;

    int lr = tid >> 2;          // 0..63
    int lc = (tid & 3) * 4;     // 0,4,8,12
    int arow = m0 + lr;
    bool arow_ok = arow < MM;
    int srcrow = arow_ok ? (gb ? gb[arow] : arow) : 0;
    const float* Aptr = Ab + (long)srcrow * K;
    const float* Bptr = W + (long)(n0 + lr) * K;

    float acc[4][4];
#pragma unroll
    for (int i = 0; i < 4; i++)
#pragma unroll
        for (int j = 0; j < 4; j++) acc[i][j] = 0.f;

    for (int k0 = 0; k0 < K; k0 += 16) {
        float4 av = arow_ok ? *(const float4*)(Aptr + k0 + lc) : make_float4(0, 0, 0, 0);
        float4 bv = *(const float4*)(Bptr + k0 + lc);
        As[lc + 0][lr] = av.x; As[lc + 1][lr] = av.y; As[lc + 2][lr] = av.z; As[lc + 3][lr] = av.w;
        Bs[lc + 0][lr] = bv.x; Bs[lc + 1][lr] = bv.y; Bs[lc + 2][lr] = bv.z; Bs[lc + 3][lr] = bv.w;
        __syncthreads();
#pragma unroll
        for (int kk = 0; kk < 16; kk++) {
            float4 a  = *(const float4*)&As[kk][ty * 4];
            float4 b4 = *(const float4*)&Bs[kk][tx * 4];
            acc[0][0] += a.x * b4.x; acc[0][1] += a.x * b4.y; acc[0][2] += a.x * b4.z; acc[0][3] += a.x * b4.w;
            acc[1][0] += a.y * b4.x; acc[1][1] += a.y * b4.y; acc[1][2] += a.y * b4.z; acc[1][3] += a.y * b4.w;
            acc[2][0] += a.z * b4.x; acc[2][1] += a.z * b4.y; acc[2][2] += a.z * b4.z; acc[2][3] += a.z * b4.w;
            acc[3][0] += a.w * b4.x; acc[3][1] += a.w * b4.y; acc[3][2] += a.w * b4.z; acc[3][3] += a.w * b4.w;
        }
        __syncthreads();
    }

    float4 bvec = *(const float4*)(bias + n0 + tx * 4);
#pragma unroll
    for (int i = 0; i < 4; i++) {
        int m = m0 + ty * 4 + i;
        if (m < MM) {
            float4 out = make_float4(acc[i][0] + bvec.x, acc[i][1] + bvec.y,
                                     acc[i][2] + bvec.z, acc[i][3] + bvec.w);
            *(float4*)(Cb + (long)m * N + n0 + tx * 4) = out;
        }
    }
}

// ---------------- l2norm + scale + RoPE, split into head-major q/k/v --------
__global__ void k_normrope(const float* __restrict__ rg) {
    int bm = blockIdx.x;               // b*MM + m
    int b = bm / MM, m = bm % MM;
    int t = threadIdx.x;
    int g = t >> 4;                    // head 0..15
    int lane = t & 15;                 // 16 threads per head, 4 elems each
    int lidx = g_idx[b * MM + m];
    const float* base = g_qkv + (size_t)bm * C3;

    float4 q4 = *(const float4*)(base + g * 64 + lane * 4);
    float4 k4 = *(const float4*)(base + CC + g * 64 + lane * 4);
    float4 v4 = *(const float4*)(base + 2 * CC + g * 64 + lane * 4);

    float sq = q4.x * q4.x + q4.y * q4.y + q4.z * q4.z + q4.w * q4.w;
    float sk = k4.x * k4.x + k4.y * k4.y + k4.z * k4.z + k4.w * k4.w;
#pragma unroll
    for (int off = 8; off > 0; off >>= 1) {
        sq += __shfl_xor_sync(0xffffffffu, sq, off, 16);
        sk += __shfl_xor_sync(0xffffffffu, sk, off, 16);
    }
    float qs = g_scl[g] / fmaxf(sqrtf(sq), 1e-12f);
    float ks = 1.f / fmaxf(sqrtf(sk), 1e-12f);

    const float* cp = rg + (size_t)lidx * 32 + lane * 2;
    const float* sp = rg + (size_t)LL * 32 + (size_t)lidx * 32 + lane * 2;
    float c0 = cp[0], c1 = cp[1], s0 = sp[0], s1 = sp[1];

    float4 qo, ko;
    qo.x = (c0 * q4.x - s0 * q4.y) * qs;
    qo.y = (s0 * q4.x + c0 * q4.y) * qs;
    qo.z = (c1 * q4.z - s1 * q4.w) * qs;
    qo.w = (s1 * q4.z + c1 * q4.w) * qs;
    ko.x = (c0 * k4.x - s0 * k4.y) * ks;
    ko.y = (s0 * k4.x + c0 * k4.y) * ks;
    ko.z = (c1 * k4.z - s1 * k4.w) * ks;
    ko.w = (s1 * k4.z + c1 * k4.w) * ks;

    size_t hoff = (((size_t)(b * NHH + g)) * MM + m) * DHH + lane * 4;
    *(float4*)(g_q + hoff) = qo;
    *(float4*)(g_k + hoff) = ko;
    *(float4*)(g_v + hoff) = v4;
}

// ---------------- attention: bounded-score softmax (no online max) ----------
// |score| <= scale_mul (q l2-normed * scale, k unit norm), so subtract the
// per-head bound once -> branch-free inner loop: 64 FMA dot + exp + 64 FMA AV.
__global__ void k_attn() {
    __shared__ float4 ks[64][16];
    __shared__ float4 vs[64][16];
    int bh = blockIdx.y;                // b*NH + h
    int q0 = blockIdx.x * 64;
    int t = threadIdx.x;
    int q = q0 + t;
    bool valid = q < MM;
    const float smax = g_scl[bh & (NHH - 1)];

    const float4* Q4 = (const float4*)(g_q + (size_t)bh * MM * DHH);
    const float4* K4 = (const float4*)(g_k + (size_t)bh * MM * DHH);
    const float4* V4 = (const float4*)(g_v + (size_t)bh * MM * DHH);

    float4 qr[16], o[16];
#pragma unroll
    for (int i = 0; i < 16; i++) {
        o[i] = make_float4(0, 0, 0, 0);
        qr[i] = valid ? Q4[(size_t)q * 16 + i] : make_float4(0, 0, 0, 0);
    }
    float lrun = 0.f;

    for (int k0 = 0; k0 < MM; k0 += 64) {
        int kn = min(64, MM - k0);
        for (int i = t; i < 64 * 16; i += 64) {
            int r = i >> 4, c2 = i & 15;
            if (k0 + r < MM) {
                ks[r][c2] = K4[(size_t)(k0 + r) * 16 + c2];
                vs[r][c2] = V4[(size_t)(k0 + r) * 16 + c2];
            }
        }
        __syncthreads();
        if (valid) {
            for (int kk = 0; kk < kn; kk++) {
                float s = 0.f;
#pragma unroll
                for (int i = 0; i < 16; i++) {
                    float4 kv = ks[kk][i];
                    s += qr[i].x * kv.x + qr[i].y * kv.y + qr[i].z * kv.z + qr[i].w * kv.w;
                }
                float p = __expf(s - smax);
                lrun += p;
#pragma unroll
                for (int i = 0; i < 16; i++) {
                    float4 vv = vs[kk][i];
                    o[i].x += p * vv.x; o[i].y += p * vv.y;
                    o[i].z += p * vv.z; o[i].w += p * vv.w;
                }
            }
        }
        __syncthreads();
    }

    if (valid) {
        float inv = 1.f / lrun;
        int b = bh >> 4, h = bh & 15;
        float4* out = (float4*)(g_ao + ((size_t)(b * MM + q)) * CC + h * DHH);
#pragma unroll
        for (int i = 0; i < 16; i++)
            out[i] = make_float4(o[i].x * inv, o[i].y * inv, o[i].z * inv, o[i].w * inv);
    }
}

// ---------------- out = x + upsample(cached_x)  (full L×C) ------------------
__global__ void k_addup(const float* __restrict__ x, const float* __restrict__ cached,
                        float* __restrict__ out) {
    int l = blockIdx.x, b = blockIdx.y, t = threadIdx.x;
    int hrow = l >> 6, wcol = l & 63;
    size_t xi = ((size_t)b * LL + l) * CC + t * 4;
    size_t ci = (((size_t)b * 32 + (hrow >> 1)) * 32 + (wcol >> 1)) * CC + t * 4;
    float4 xv = *(const float4*)(x + xi);
    float4 cv = *(const float4*)(cached + ci);
    *(float4*)(out + xi) = make_float4(xv.x + cv.x, xv.y + cv.y, xv.z + cv.z, xv.w + cv.w);
}

// ---------------- overwrite selected rows: out[idx] = x[idx] + proj ---------
__global__ void k_scatter(const float* __restrict__ x, float* __restrict__ out) {
    int m = blockIdx.x, b = blockIdx.y, t = threadIdx.x;
    int l = g_idx[b * MM + m];
    size_t oi = ((size_t)b * LL + l) * CC + t * 4;
    size_t pi = ((size_t)b * MM + m) * CC + t * 4;
    float4 xv = *(const float4*)(x + oi);
    float4 pv = *(const float4*)(g_po + pi);
    *(float4*)(out + oi) = make_float4(xv.x + pv.x, xv.y + pv.y, xv.z + pv.z, xv.w + pv.w);
}

// ---------------- launch -----------------------------------------------------
extern "C" void kernel_launch(void* const* d_in, const int* in_sizes, int n_in,
                              void* d_out, int out_size) {
    (void)in_sizes; (void)n_in; (void)out_size;
    const float* x        = (const float*)d_in[0];
    const float* cached_x = (const float*)d_in[1];
    const float* W_qkv    = (const float*)d_in[2];
    const float* q_bias   = (const float*)d_in[3];
    const float* v_bias   = (const float*)d_in[4];
    const float* W_proj   = (const float*)d_in[5];
    const float* b_proj   = (const float*)d_in[6];
    const float* sml      = (const float*)d_in[7];
    const float* rope     = (const float*)d_in[8];
    float* out = (float*)d_out;

    k_mean_part<<<dim3(CC / 256, BB, LSPLIT), 256>>>(x);
    k_mean_final<<<(BB * CC) / 256, 256>>>();
    k_mse<<<dim3(LL, BB), 256>>>(x);
    k_topk<<<BB, 1024>>>();
    k_bias3<<<C3 / 256, 256>>>(q_bias, v_bias, sml);
    // QKV GEMM: M=1638 rows (gathered), N=3072, K=1024
    k_gemm<<<dim3(C3 / 64, (MM + 63) / 64, BB), 256>>>(0, x, W_qkv, (const float*)0);
    k_normrope<<<BB * MM, 256>>>(rope);
    k_attn<<<dim3((MM + 63) / 64, BB * NHH), 64>>>();
    // proj GEMM: M=1638, N=1024, K=1024
    k_gemm<<<dim3(CC / 64, (MM + 63) / 64, BB), 256>>>(1, (const float*)0, W_proj, b_proj);
    k_addup<<<dim3(LL, BB), 256>>>(x, cached_x, out);
    k_scatter<<<dim3(MM, BB), 256>>>(x, out);
}